// round 1
// baseline (speedup 1.0000x reference)
#include <cuda_runtime.h>
#include <cstdint>

#define N_CAR   180000
#define E_NUM   6400000
#define NPARAM  (4096*4096)

// ---------------- device scratch (no allocations allowed) ----------------
__device__ int    g_segmax[N_CAR];   // float bits of per-car segment max; -1 = empty (== -inf)
__device__ double g_acc[7];          // 0:bce 1:mse 2:violcnt 3:beta 4:gat_sum 5:gat_cnt 6:reg

// ---------------- init: reset scratch every replay ----------------
__global__ void init_kernel() {
    int i = blockIdx.x * blockDim.x + threadIdx.x;
    if (i < N_CAR) g_segmax[i] = -1;
    if (i < 7)     g_acc[i] = 0.0;
}

// ---------------- edge kernel: segment-max of alpha over src, rule edges only ----------------
// rule_edge <=> dst entity type in {1,2} <=> dst >= N_CAR (cars are nodes [0, N_CAR)).
__global__ void edge_kernel(const int* __restrict__ src,
                            const int* __restrict__ dst,
                            const float* __restrict__ alpha) {
    int i = blockIdx.x * blockDim.x + threadIdx.x;
    if (i >= E_NUM / 4) return;

    int4 d = __ldg(reinterpret_cast<const int4*>(dst) + i);
    bool q0 = d.x >= N_CAR, q1 = d.y >= N_CAR, q2 = d.z >= N_CAR, q3 = d.w >= N_CAR;
    if (!(q0 | q1 | q2 | q3)) return;   // ~66% of threads skip src+alpha loads

    int4   s = __ldg(reinterpret_cast<const int4*>(src) + i);
    float4 a = __ldg(reinterpret_cast<const float4*>(alpha) + i);

    // alpha >= 0, so int-bit compare preserves float ordering; -1 sentinel is below all.
    if (q0 && s.x < N_CAR) atomicMax(&g_segmax[s.x], __float_as_int(a.x));
    if (q1 && s.y < N_CAR) atomicMax(&g_segmax[s.y], __float_as_int(a.y));
    if (q2 && s.z < N_CAR) atomicMax(&g_segmax[s.z], __float_as_int(a.z));
    if (q3 && s.w < N_CAR) atomicMax(&g_segmax[s.w], __float_as_int(a.w));
}

// ---------------- block reduction helper ----------------
template <int K>
__device__ __forceinline__ void block_reduce_accum(float (&v)[K], double* gbase) {
    __shared__ float sh[K][8];
    int lane = threadIdx.x & 31;
    int w    = threadIdx.x >> 5;
#pragma unroll
    for (int k = 0; k < K; k++) {
        float x = v[k];
#pragma unroll
        for (int o = 16; o; o >>= 1) x += __shfl_down_sync(0xffffffffu, x, o);
        if (lane == 0) sh[k][w] = x;
    }
    __syncthreads();
    if (threadIdx.x < K) {
        float s = 0.f;
#pragma unroll
        for (int j = 0; j < 8; j++) s += sh[threadIdx.x][j];
        atomicAdd(&gbase[threadIdx.x], (double)s);
    }
}

// ---------------- per-car losses: BCE, MSE, violation count, beta loss, GAT loss ----------------
__global__ void car_kernel(const float* __restrict__ model,
                           const float* __restrict__ rule,
                           const float* __restrict__ beta) {
    int i = blockIdx.x * blockDim.x + threadIdx.x;
    float v[6] = {0.f, 0.f, 0.f, 0.f, 0.f, 0.f};  // bce, mse, viol, beta, gat_sum, gat_cnt
    if (i < N_CAR) {
        float m = model[i], r = rule[i];
        // x in [1e-6, 1-1e-6] so logs never hit the -100 clamp
        float lx  = logf(m);
        float l1x = log1pf(-m);
        v[0] = -(r * lx + (1.0f - r) * l1x);
        float d = m - r;
        v[1] = d * d;
        if (r > 0.5f) {
            v[2] = 1.f;
            float b = beta[i];
            v[3] = (1.f - b) * (1.f - b);
            int sm = g_segmax[i];
            if (sm >= 0) {                     // had at least one rule edge (finite max)
                float mx = __int_as_float(sm);
                v[4] = (1.f - mx) * (1.f - mx);
                v[5] = 1.f;
            }
        }
    }
    block_reduce_accum<6>(v, &g_acc[0]);
}

// ---------------- L2 regularization: sum(p0^2) + sum(p1^2) ----------------
__global__ void param_kernel(const float* __restrict__ p0, const float* __restrict__ p1) {
    const int n4 = NPARAM / 4;
    float acc = 0.f;
    int stride = gridDim.x * blockDim.x;
    for (int i = blockIdx.x * blockDim.x + threadIdx.x; i < n4; i += stride) {
        float4 a = __ldg(reinterpret_cast<const float4*>(p0) + i);
        float4 b = __ldg(reinterpret_cast<const float4*>(p1) + i);
        acc += a.x*a.x + a.y*a.y + a.z*a.z + a.w*a.w;
        acc += b.x*b.x + b.y*b.y + b.z*b.z + b.w*b.w;
    }
    float v[1] = {acc};
    block_reduce_accum<1>(v, &g_acc[6]);
}

// ---------------- combine ----------------
__global__ void final_kernel(float* __restrict__ out) {
    double bce  = g_acc[0], mse = g_acc[1], viol = g_acc[2];
    double bsum = g_acc[3], gsum = g_acc[4], gcnt = g_acc[5], reg = g_acc[6];

    float L_recon     = (float)(bce / (double)N_CAR);
    float L_rule      = (float)(mse / (double)N_CAR);
    float L_attn_gat  = (viol > 0.0 && gcnt > 0.0) ? (float)(gsum / gcnt) : 0.f;
    float L_attn_rule = (viol > 0.0) ? (float)(bsum / viol) : 0.f;
    float L_attn      = 0.5f * L_attn_gat + 0.5f * L_attn_rule;
    float L_reg       = (float)reg;
    float L_total     = 1.0f * L_recon + 0.5f * L_rule + 0.3f * L_attn + 1e-4f * L_reg;

    out[0] = L_total;
    out[1] = L_recon;
    out[2] = L_rule;
    out[3] = L_attn;
    out[4] = L_attn_gat;
    out[5] = L_attn_rule;
    out[6] = L_reg;
    out[7] = (float)viol;
}

// ---------------- launcher ----------------
extern "C" void kernel_launch(void* const* d_in, const int* in_sizes, int n_in,
                              void* d_out, int out_size) {
    const float* model = (const float*)d_in[0];
    const float* rule  = (const float*)d_in[1];
    const float* alpha = (const float*)d_in[2];
    const float* beta  = (const float*)d_in[3];
    const int*   eidx  = (const int*)d_in[4];   // [2, E] stacked: row0=src, row1=dst
    // d_in[5] entity_types: structural (cars first) -> replaced by dst >= N_CAR
    const float* p0    = (const float*)d_in[6];
    const float* p1    = (const float*)d_in[7];
    float* out = (float*)d_out;

    init_kernel<<<(N_CAR + 255) / 256, 256>>>();
    edge_kernel<<<(E_NUM / 4 + 255) / 256, 256>>>(eidx, eidx + E_NUM, alpha);
    param_kernel<<<1184, 256>>>(p0, p1);
    car_kernel<<<(N_CAR + 255) / 256, 256>>>(model, rule, beta);
    final_kernel<<<1, 1>>>(out);
}

// round 2
// speedup vs baseline: 1.0471x; 1.0471x over previous
#include <cuda_runtime.h>
#include <cstdint>

#define N_CAR   180000
#define E_NUM   6400000
#define NP4     (4096*4096/4)   // float4 count per param
#define NC4     (N_CAR/4)       // 45000
#define NE4     (E_NUM/4)       // 1.6M

// ---------------- device scratch (no allocations allowed) ----------------
__device__ int    g_segmax[N_CAR];  // float bits of per-car max; -1 sentinel == -inf
// slots: 0 bce, 1 mse, 2 viol, 3 beta, 4 reg, 5 gat_sum, 6 gat_cnt
__device__ double g_acc[7];

// ---------------- block reduction -> atomic accumulate ----------------
template <int K>
__device__ __forceinline__ void block_reduce_accum(float (&v)[K], double* gbase) {
    __shared__ float sh[K][8];
    int lane = threadIdx.x & 31;
    int w    = threadIdx.x >> 5;
#pragma unroll
    for (int k = 0; k < K; k++) {
        float x = v[k];
#pragma unroll
        for (int o = 16; o; o >>= 1) x += __shfl_down_sync(0xffffffffu, x, o);
        if (lane == 0) sh[k][w] = x;
    }
    __syncthreads();
    if (threadIdx.x < K) {
        float s = 0.f;
#pragma unroll
        for (int j = 0; j < 8; j++) s += sh[threadIdx.x][j];
        atomicAdd(&gbase[threadIdx.x], (double)s);
    }
}

// ---------------- init: reset scratch every replay (vectorized) ----------------
__global__ void init_kernel() {
    int i = blockIdx.x * blockDim.x + threadIdx.x;
    if (i < NC4) reinterpret_cast<int4*>(g_segmax)[i] = make_int4(-1, -1, -1, -1);
    if (i < 7)   g_acc[i] = 0.0;
}

// ---------------- fused streaming kernel: param reg + score losses + edge segmax ----
// These three workloads are mutually independent; fusing them keeps HBM saturated
// instead of paying three sub-saturating kernels + launch gaps.
__global__ void main_kernel(const float* __restrict__ model,
                            const float* __restrict__ rule,
                            const float* __restrict__ beta,
                            const float* __restrict__ alpha,
                            const int*   __restrict__ src,
                            const int*   __restrict__ dst,
                            const float* __restrict__ p0,
                            const float* __restrict__ p1) {
    const int tid    = blockIdx.x * blockDim.x + threadIdx.x;
    const int stride = gridDim.x * blockDim.x;

    // --- L2 regularization: 134 MB, the dominant stream ---
    float reg = 0.f;
#pragma unroll 2
    for (int i = tid; i < NP4; i += stride) {
        float4 a = __ldg(reinterpret_cast<const float4*>(p0) + i);
        float4 b = __ldg(reinterpret_cast<const float4*>(p1) + i);
        reg += a.x*a.x + a.y*a.y + a.z*a.z + a.w*a.w;
        reg += b.x*b.x + b.y*b.y + b.z*b.z + b.w*b.w;
    }

    // --- per-car BCE / MSE / violation count / beta loss (no segmax needed) ---
    float bce = 0.f, mse = 0.f, viol = 0.f, bsum = 0.f;
    for (int i = tid; i < NC4; i += stride) {
        float4 m = __ldg(reinterpret_cast<const float4*>(model) + i);
        float4 r = __ldg(reinterpret_cast<const float4*>(rule)  + i);
        float4 b = __ldg(reinterpret_cast<const float4*>(beta)  + i);
        const float mm[4] = {m.x, m.y, m.z, m.w};
        const float rr[4] = {r.x, r.y, r.z, r.w};
        const float bb[4] = {b.x, b.y, b.z, b.w};
#pragma unroll
        for (int j = 0; j < 4; j++) {
            // inputs clipped to [1e-6, 1-1e-6] -> logs never hit the -100 clamp
            float lx  = logf(mm[j]);
            float l1x = log1pf(-mm[j]);
            bce += -(rr[j] * lx + (1.0f - rr[j]) * l1x);
            float d = mm[j] - rr[j];
            mse += d * d;
            if (rr[j] > 0.5f) {
                viol += 1.f;
                float ob = 1.f - bb[j];
                bsum += ob * ob;
            }
        }
    }

    // --- edge segment-max: rule edge <=> dst >= N_CAR (cars are nodes [0, N_CAR)) ---
    for (int i = tid; i < NE4; i += stride) {
        int4 d = __ldg(reinterpret_cast<const int4*>(dst) + i);
        bool q0 = d.x >= N_CAR, q1 = d.y >= N_CAR, q2 = d.z >= N_CAR, q3 = d.w >= N_CAR;
        if (!(q0 | q1 | q2 | q3)) continue;  // ~66% skip src+alpha loads entirely
        int4   s = __ldg(reinterpret_cast<const int4*>(src) + i);
        float4 a = __ldg(reinterpret_cast<const float4*>(alpha) + i);
        // alpha >= 0 -> int-bit compare preserves float order; -1 sentinel below all
        if (q0 && s.x < N_CAR) atomicMax(&g_segmax[s.x], __float_as_int(a.x));
        if (q1 && s.y < N_CAR) atomicMax(&g_segmax[s.y], __float_as_int(a.y));
        if (q2 && s.z < N_CAR) atomicMax(&g_segmax[s.z], __float_as_int(a.z));
        if (q3 && s.w < N_CAR) atomicMax(&g_segmax[s.w], __float_as_int(a.w));
    }

    float v[5] = {bce, mse, viol, bsum, reg};
    block_reduce_accum<5>(v, &g_acc[0]);
}

// ---------------- GAT attention loss: needs completed segmax ----------------
__global__ void gat_kernel(const float* __restrict__ rule) {
    int i = blockIdx.x * blockDim.x + threadIdx.x;
    float gs = 0.f, gc = 0.f;
    if (i < NC4) {
        float4 r  = __ldg(reinterpret_cast<const float4*>(rule) + i);
        int4   sm = reinterpret_cast<const int4*>(g_segmax)[i];
        const float rr[4] = {r.x, r.y, r.z, r.w};
        const int   ss[4] = {sm.x, sm.y, sm.z, sm.w};
#pragma unroll
        for (int j = 0; j < 4; j++) {
            if (rr[j] > 0.5f && ss[j] >= 0) {   // violating car with >=1 rule edge
                float mx = __int_as_float(ss[j]);
                float om = 1.f - mx;
                gs += om * om;
                gc += 1.f;
            }
        }
    }
    float v[2] = {gs, gc};
    block_reduce_accum<2>(v, &g_acc[5]);
}

// ---------------- combine ----------------
__global__ void final_kernel(float* __restrict__ out) {
    double bce  = g_acc[0], mse = g_acc[1], viol = g_acc[2];
    double bsum = g_acc[3], reg = g_acc[4], gsum = g_acc[5], gcnt = g_acc[6];

    float L_recon     = (float)(bce / (double)N_CAR);
    float L_rule      = (float)(mse / (double)N_CAR);
    float L_attn_gat  = (viol > 0.0 && gcnt > 0.0) ? (float)(gsum / gcnt) : 0.f;
    float L_attn_rule = (viol > 0.0) ? (float)(bsum / viol) : 0.f;
    float L_attn      = 0.5f * L_attn_gat + 0.5f * L_attn_rule;
    float L_reg       = (float)reg;
    float L_total     = 1.0f * L_recon + 0.5f * L_rule + 0.3f * L_attn + 1e-4f * L_reg;

    out[0] = L_total;
    out[1] = L_recon;
    out[2] = L_rule;
    out[3] = L_attn;
    out[4] = L_attn_gat;
    out[5] = L_attn_rule;
    out[6] = L_reg;
    out[7] = (float)viol;
}

// ---------------- launcher ----------------
extern "C" void kernel_launch(void* const* d_in, const int* in_sizes, int n_in,
                              void* d_out, int out_size) {
    const float* model = (const float*)d_in[0];
    const float* rule  = (const float*)d_in[1];
    const float* alpha = (const float*)d_in[2];
    const float* beta  = (const float*)d_in[3];
    const int*   eidx  = (const int*)d_in[4];   // [2, E]: row0=src, row1=dst
    // d_in[5] entity_types: structural (cars first) -> replaced by dst >= N_CAR
    const float* p0    = (const float*)d_in[6];
    const float* p1    = (const float*)d_in[7];
    float* out = (float*)d_out;

    init_kernel<<<(NC4 + 255) / 256, 256>>>();                       // 176 blocks
    main_kernel<<<1184, 256>>>(model, rule, beta, alpha,
                               eidx, eidx + E_NUM, p0, p1);          // 8 blocks/SM
    gat_kernel<<<(NC4 + 255) / 256, 256>>>(rule);
    final_kernel<<<1, 1>>>(out);
}